// round 9
// baseline (speedup 1.0000x reference)
#include <cuda_runtime.h>
#include <cuda_bf16.h>

// RUDY congestion map via 2D difference-array + summed-area reconstruction.
//
// Diff accumulators (both zero at entry/exit of every launch):
//   E: interleaved {H,V} at (px*DPITCH+y)*2        -- even-start y-pairs
//   O: interleaved {H,V} at px*1024 + (y-1)*2      -- odd-start y-pairs
//      (O is E shifted by one y; cell for pair (y0,y0+1), y0 odd, is 16B
//       aligned, so EVERY adjacent y-pair is one red.global.add.v4.f32.)
// Pipeline (3 launches):
//   scatter : 4 lanes/net; quad shfl bbox; lane sub owns x-breakpoint sub and
//             issues exactly <=2 v4 REDs (lo-pair, hi-pair).  8 REDs/net.
//   row_scan: y-scan of E[y]+O[y-1] per x-row; zero-restores O.
//   col_scan: x-scan per y-column, out = max(|h|,|v|); zero-restores E.

#define NBX 512
#define NBY 512
#define DPITCH 516          // E row pitch (cols 0..511 used); mult of 4
#define DROWS  513

__device__ float g_diffE[DROWS * DPITCH * 2];   // zero-init
__device__ float g_diffO[NBX * 1024];           // 512 rows x 512 {H,V} pairs

__device__ __forceinline__ float edge(int i, float bs) {
    return (float)i * bs;   // bs = 1000/512 = 125/64 exact; i*bs exact here
}

// overlap of [vmin, vmax] with bin i, clipped to [0, bs] — identical formula
// to the reference's clip(min(vmax, e[i+1]) - max(vmin, e[i]), 0, bs).
__device__ __forceinline__ float fval(float vmin, float vmax, int i, float bs) {
    float lo_e = edge(i, bs);
    float hi_e = edge(i + 1, bs);
    float ov = fminf(vmax, hi_e) - fmaxf(vmin, lo_e);
    return fminf(fmaxf(ov, 0.0f), bs);
}

// exact bin index of v (0..nb-1), correcting fp error in the division against
// the exactly-representable edges.
__device__ __forceinline__ int bin_of(float v, float inv_bs, float bs, int nb) {
    int i = (int)(v * inv_bs);
    if (i > nb - 1) i = nb - 1;
    if (i < 0) i = 0;
    if (i > 0 && v < edge(i, bs)) --i;
    else if (i < nb - 1 && v >= edge(i + 1, bs)) ++i;
    return i;
}

__device__ __forceinline__ void red_add_v4(float* p, float a, float b,
                                           float c, float d) {
    asm volatile("red.global.add.v4.f32 [%0], {%1, %2, %3, %4};"
                 :: "l"(p), "f"(a), "f"(b), "f"(c), "f"(d) : "memory");
}

__global__ void scatter_kernel(const float* __restrict__ pin_pos,
                               const float* __restrict__ net_weights,
                               const int* __restrict__ netpin_start,
                               const int* __restrict__ flat_netpin,
                               int num_nets, int P) {
    const float BSX = 1.953125f;          // 1000/512, exact
    const float BSY = 1.953125f;
    const float INV_BSX = 1.0f / 1.953125f;
    const float INV_BSY = 1.0f / 1.953125f;
    const float SCALE = 262144.0f / 100000.0f;  // 1/(BSX*BSY*0.1)

    int gt = blockIdx.x * blockDim.x + threadIdx.x;
    int n = gt >> 2;          // one net per quad of lanes
    int sub = gt & 3;
    bool valid = (n < num_nets);

    float xmin = 3.0e38f, xmax = -3.0e38f, ymin = 3.0e38f, ymax = -3.0e38f;
    int s = 0, cnt = 0;
    if (valid) {
        s = netpin_start[n];
        cnt = netpin_start[n + 1] - s;
    }

    // lane sub gathers pins sub, sub+4 (covers cnt<=8), fallback for more
    if (sub < cnt) {
        int id = __ldg(&flat_netpin[s + sub]);
        float x = __ldg(&pin_pos[id]);
        float y = __ldg(&pin_pos[P + id]);
        xmin = fminf(xmin, x); xmax = fmaxf(xmax, x);
        ymin = fminf(ymin, y); ymax = fmaxf(ymax, y);
    }
    if (sub + 4 < cnt) {
        int id = __ldg(&flat_netpin[s + sub + 4]);
        float x = __ldg(&pin_pos[id]);
        float y = __ldg(&pin_pos[P + id]);
        xmin = fminf(xmin, x); xmax = fmaxf(xmax, x);
        ymin = fminf(ymin, y); ymax = fmaxf(ymax, y);
    }
    for (int k = sub + 8; k < cnt; k += 4) {
        int id = __ldg(&flat_netpin[s + k]);
        float x = __ldg(&pin_pos[id]);
        float y = __ldg(&pin_pos[P + id]);
        xmin = fminf(xmin, x); xmax = fmaxf(xmax, x);
        ymin = fminf(ymin, y); ymax = fmaxf(ymax, y);
    }

    // quad butterfly: combine bbox across 4 lanes (xor 1, then 2).
    // Whole warp executes (no early return above); quads never mix.
#pragma unroll
    for (int o = 1; o <= 2; o <<= 1) {
        xmin = fminf(xmin, __shfl_xor_sync(0xffffffff, xmin, o));
        xmax = fmaxf(xmax, __shfl_xor_sync(0xffffffff, xmax, o));
        ymin = fminf(ymin, __shfl_xor_sync(0xffffffff, ymin, o));
        ymax = fmaxf(ymax, __shfl_xor_sync(0xffffffff, ymax, o));
    }

    if (!valid) return;

    float sx = xmax - xmin;
    float sy = ymax - ymin;
    // zero span in either dim zeroes the ox*oy product for BOTH maps
    if (!(sx > 0.0f) || !(sy > 0.0f)) return;

    float wt = __ldg(&net_weights[n]) * SCALE;
    float wh = wt / sy;   // horizontal demand weight
    float wv = wt / sx;   // vertical demand weight

    int lox = bin_of(xmin, INV_BSX, BSX, NBX);
    int hix = bin_of(xmax, INV_BSX, BSX, NBX);
    int loy = bin_of(ymin, INV_BSY, BSY, NBY);
    int hiy = bin_of(ymax, INV_BSY, BSY, NBY);

    // lane sub owns x-breakpoint sub: {lox, lox+1, hix, hix+1} with dedup.
    int px = (sub < 2) ? (lox + sub) : (hix + (sub - 2));
    bool xok = (sub < 2) || (sub == 2 ? (hix > lox + 1) : (hix > lox));
    if (!xok || px >= NBX) return;     // index-512 positions are dead

    float dx = fval(xmin, xmax, px, BSX) - fval(xmin, xmax, px - 1, BSX);
    float ah = wh * dx;
    float av = wv * dx;

    // lo pair (loy, loy+1): both positions always in the support
    {
        float f0 = fval(ymin, ymax, loy, BSY);
        float d0 = f0;                                      // fval(loy-1)=0
        float d1 = fval(ymin, ymax, loy + 1, BSY) - f0;
        float* p = (loy & 1)
            ? &g_diffO[px * 1024 + (loy - 1) * 2]
            : &g_diffE[(px * DPITCH + loy) * 2];
        red_add_v4(p, ah * d0, av * d0, ah * d1, av * d1);
    }
    // hi pair (hiy, hiy+1): hiy only if hiy>loy+1, hiy+1 only if hiy>loy.
    // (position 512 lands in a dead slot of O, restored by row_scan.)
    if (hiy > loy) {
        float fh = fval(ymin, ymax, hiy, BSY);
        float e0 = (hiy > loy + 1)
                 ? (fh - fval(ymin, ymax, hiy - 1, BSY)) : 0.0f;
        float e1 = fval(ymin, ymax, hiy + 1, BSY) - fh;
        float* p = (hiy & 1)
            ? &g_diffO[px * 1024 + (hiy - 1) * 2]
            : &g_diffE[(px * DPITCH + hiy) * 2];
        red_add_v4(p, ah * e0, av * e0, ah * e1, av * e1);
    }
}

// inclusive scan along y per x-row of E[y]+O[y-1]; zero-restores O.
__global__ void row_scan_kernel() {
    __shared__ float wsH[16];
    __shared__ float wsV[16];
    int row = blockIdx.x;
    int t = threadIdx.x;            // y
    int lane = t & 31, wid = t >> 5;

    float2* E = reinterpret_cast<float2*>(g_diffE) + row * DPITCH;
    float2* O = reinterpret_cast<float2*>(g_diffO) + row * 512;

    float2 hv = E[t];
    float h = hv.x, v = hv.y;
    if (t >= 1) {
        float2 o = O[t - 1];
        h += o.x; v += o.y;
        O[t - 1] = make_float2(0.f, 0.f);      // restore zeros
    } else {
        O[511] = make_float2(0.f, 0.f);        // dead y=512 slot
    }

#pragma unroll
    for (int o = 1; o < 32; o <<= 1) {
        float nh = __shfl_up_sync(0xffffffff, h, o);
        float nv = __shfl_up_sync(0xffffffff, v, o);
        if (lane >= o) { h += nh; v += nv; }
    }
    if (lane == 31) { wsH[wid] = h; wsV[wid] = v; }
    __syncthreads();
    if (wid == 0) {
        float sv = (lane < 16) ? wsH[lane] : wsV[lane - 16];
#pragma unroll
        for (int o = 1; o < 16; o <<= 1) {
            float nv = __shfl_up_sync(0xffffffff, sv, o, 16);
            if ((lane & 15) >= o) sv += nv;
        }
        if (lane < 16) wsH[lane] = sv; else wsV[lane - 16] = sv;
    }
    __syncthreads();
    if (wid > 0) { h += wsH[wid - 1]; v += wsV[wid - 1]; }
    E[t] = make_float2(h, v);
}

// parallel inclusive scan along x for FOUR y-columns per block (2x float4 =
// {H,V} x 4 columns per thread), finalize max(|h|,|v|), restore E zeros.
// 128 blocks x 512 threads.
__global__ void col_scan_finalize_kernel(float* __restrict__ out) {
    __shared__ float ws[8][16];
    int y0 = blockIdx.x * 4;     // first of four columns
    int t = threadIdx.x;         // x index
    int lane = t & 31, wid = t >> 5;

    float* base = &g_diffE[(t * DPITCH + y0) * 2];   // 16B aligned
    float4 qa = *reinterpret_cast<const float4*>(base);
    float4 qb = *reinterpret_cast<const float4*>(base + 4);
    float s0 = qa.x, s1 = qa.y, s2 = qa.z, s3 = qa.w;  // H(y0),V(y0),H(y1),V(y1)
    float s4 = qb.x, s5 = qb.y, s6 = qb.z, s7 = qb.w;  // H(y2),V(y2),H(y3),V(y3)

#pragma unroll
    for (int o = 1; o < 32; o <<= 1) {
        float n0 = __shfl_up_sync(0xffffffff, s0, o);
        float n1 = __shfl_up_sync(0xffffffff, s1, o);
        float n2 = __shfl_up_sync(0xffffffff, s2, o);
        float n3 = __shfl_up_sync(0xffffffff, s3, o);
        float n4 = __shfl_up_sync(0xffffffff, s4, o);
        float n5 = __shfl_up_sync(0xffffffff, s5, o);
        float n6 = __shfl_up_sync(0xffffffff, s6, o);
        float n7 = __shfl_up_sync(0xffffffff, s7, o);
        if (lane >= o) {
            s0 += n0; s1 += n1; s2 += n2; s3 += n3;
            s4 += n4; s5 += n5; s6 += n6; s7 += n7;
        }
    }
    if (lane == 31) {
        ws[0][wid] = s0; ws[1][wid] = s1; ws[2][wid] = s2; ws[3][wid] = s3;
        ws[4][wid] = s4; ws[5][wid] = s5; ws[6][wid] = s6; ws[7][wid] = s7;
    }
    __syncthreads();

    // warps 0..7 each scan one 16-long warp-sum sequence (lanes 0..15 active)
    if (wid < 8 && lane < 16) {
        float sv = ws[wid][lane];
#pragma unroll
        for (int o = 1; o < 16; o <<= 1) {
            float nv = __shfl_up_sync(0x0000ffff, sv, o, 16);
            if (lane >= o) sv += nv;
        }
        ws[wid][lane] = sv;
    }
    __syncthreads();

    if (wid > 0) {
        s0 += ws[0][wid - 1]; s1 += ws[1][wid - 1];
        s2 += ws[2][wid - 1]; s3 += ws[3][wid - 1];
        s4 += ws[4][wid - 1]; s5 += ws[5][wid - 1];
        s6 += ws[6][wid - 1]; s7 += ws[7][wid - 1];
    }

    // restore zeros so the next kernel_launch call starts from a clean array
    float4 z = make_float4(0.f, 0.f, 0.f, 0.f);
    *reinterpret_cast<float4*>(base) = z;
    *reinterpret_cast<float4*>(base + 4) = z;

    // out[x][y] row-major; x*512 + y0 is a multiple of 4 -> float4 store
    *reinterpret_cast<float4*>(&out[t * NBY + y0]) =
        make_float4(fmaxf(fabsf(s0), fabsf(s1)), fmaxf(fabsf(s2), fabsf(s3)),
                    fmaxf(fabsf(s4), fabsf(s5)), fmaxf(fabsf(s6), fabsf(s7)));
}

extern "C" void kernel_launch(void* const* d_in, const int* in_sizes, int n_in,
                              void* d_out, int out_size) {
    const float* pin_pos      = (const float*)d_in[0];
    const float* net_weights  = (const float*)d_in[1];
    const int*   netpin_start = (const int*)d_in[2];
    const int*   flat_netpin  = (const int*)d_in[3];
    float* out = (float*)d_out;

    int P = in_sizes[0] / 2;
    int num_nets = in_sizes[2] - 1;

    int threads = num_nets * 4;
    scatter_kernel<<<(threads + 255) / 256, 256>>>(
        pin_pos, net_weights, netpin_start, flat_netpin, num_nets, P);
    row_scan_kernel<<<NBX, NBY>>>();
    col_scan_finalize_kernel<<<NBY / 4, NBX>>>(out);
}